// round 12
// baseline (speedup 1.0000x reference)
#include <cuda_runtime.h>
#include <cstdint>

#define T_LEN 6000
#define BATCH 64
#define HID   128
#define PROJ  32
#define G4    512

typedef unsigned long long u64;

// ---------------- scratch ----------------
__device__ float g_xi [(size_t)T_LEN * BATCH * G4];    // xi0 (X -> C0)
__device__ float g_xi1[(size_t)T_LEN * BATCH * G4];    // xi1 (G -> C1)
__device__ float g_h0 [(size_t)T_LEN * BATCH * PROJ];  // h0  (C0 -> G)
__device__ int   g_wmx[BATCH];                         // xi0 watermark
__device__ int   g_wm0[BATCH];                         // h0 watermark
__device__ int   g_wm1[BATCH];                         // xi1 watermark

// ---------------- f32x2 helpers ----------------
__device__ __forceinline__ u64 pk(float lo, float hi) {
    u64 r;
    asm("mov.b64 %0, {%1, %2};" : "=l"(r) : "f"(lo), "f"(hi));
    return r;
}
__device__ __forceinline__ void upk(u64 a, float& lo, float& hi) {
    asm("mov.b64 {%0, %1}, %2;" : "=f"(lo), "=f"(hi) : "l"(a));
}
__device__ __forceinline__ void fma2(u64& d, u64 a, u64 b) {
    asm("fma.rn.f32x2 %0, %1, %2, %3;" : "=l"(d) : "l"(a), "l"(b), "l"(d));
}
__device__ __forceinline__ u64 add2(u64 a, u64 b) {
    u64 r;
    asm("add.rn.f32x2 %0, %1, %2;" : "=l"(r) : "l"(a), "l"(b));
    return r;
}
__device__ __forceinline__ float hsum(u64 a) {
    float lo, hi; upk(a, lo, hi); return lo + hi;
}

// ---------------- activations ----------------
__device__ __forceinline__ float tanh_hw(float x) {
    float r; asm("tanh.approx.f32 %0, %1;" : "=f"(r) : "f"(x)); return r;
}
__device__ __forceinline__ float sigm(float x) {
    return fmaf(tanh_hw(x * 0.5f), 0.5f, 0.5f);
}
__device__ __forceinline__ float ex2_(float x) {
    float r; asm("ex2.approx.f32 %0, %1;" : "=f"(r) : "f"(x)); return r;
}
__device__ __forceinline__ float rcp_(float x) {
    float r; asm("rcp.approx.f32 %0, %1;" : "=f"(r) : "f"(x)); return r;
}
__device__ __forceinline__ float sigm_acc(float x) {
    return rcp_(1.f + ex2_(-x * 1.4426950408889634f));
}

// ---------------- flag ops ----------------
__device__ __forceinline__ void wm_store(int* p, int v) {
    asm volatile("st.release.gpu.global.s32 [%0], %1;" :: "l"(p), "r"(v) : "memory");
}
__device__ __forceinline__ int wm_load(const int* p) {
    int v;
    asm volatile("ld.acquire.gpu.global.s32 %0, [%1];" : "=r"(v) : "l"(p) : "memory");
    return v;
}

__global__ void init_wm() {
    if (threadIdx.x < BATCH) {
        g_wmx[threadIdx.x] = 0;
        g_wm0[threadIdx.x] = 0;
        g_wm1[threadIdx.x] = 0;
    }
}

// ---------------- LSTM cell body (C0 / C1), R7 cadence ----------------
template<bool EMIT_H0, bool EMIT_OUT>
__device__ __forceinline__ void cell_phase(
    int b, const float* __restrict__ xsrc, const int* __restrict__ wm_in,
    int* __restrict__ wm_out, const float* __restrict__ Whh,
    const float* __restrict__ Whr, const float* __restrict__ W2,
    const float* __restrict__ b2, float* __restrict__ h0out,
    float* __restrict__ out)
{
    const int u = threadIdx.x;
    const int w = u >> 5, l = u & 31;

    __shared__ __align__(16) float ots[128];
    __shared__ __align__(16) float hp[2][4][32];
    __shared__ __align__(16) float hbw[4][32];

    u64 whh[4][16];
#pragma unroll
    for (int q = 0; q < 4; q++) {
        const u64* p = reinterpret_cast<const u64*>(Whh + (q * HID + u) * PROJ);
#pragma unroll
        for (int j = 0; j < 16; j++) whh[q][j] = p[j];
    }
    u64 whr[16];
    {
        const u64* wr = reinterpret_cast<const u64*>(Whr + l * HID + w * 32);
#pragma unroll
        for (int j = 0; j < 16; j++) whr[j] = wr[j];
    }
    float w2v = 0.f, b2v = 0.f;
    if (EMIT_OUT) { w2v = W2[l]; b2v = b2[0]; }

    hbw[w][l] = 0.f;
    float c = 0.f;
    __syncthreads();

    const size_t strideT = (size_t)BATCH * G4;
    const float* xp = xsrc + (size_t)b * G4 + u;

    int wmv = 0;
    if (wm_in) { while ((wmv = wm_load(wm_in)) < 8) __nanosleep(200); }

    float buf[4][4];
#pragma unroll
    for (int k = 0; k < 4; k++) {
        const float* xn = xp + (size_t)k * strideT;
#pragma unroll
        for (int q = 0; q < 4; q++) buf[k][q] = xn[q * HID];
    }

    for (int t4 = 0; t4 < T_LEN / 4; t4++) {
        if (wm_in && t4) {
            int need = t4 * 4 + 8; if (need > T_LEN) need = T_LEN;
            while (wmv < need) { wmv = wm_load(wm_in); if (wmv < need) __nanosleep(100); }
        }
#pragma unroll
        for (int k = 0; k < 4; k++) {
            const int t = t4 * 4 + k;
            float g0 = buf[k][0], g1 = buf[k][1], g2 = buf[k][2], g3 = buf[k][3];
            if (t + 4 < T_LEN) {
                const float* xn = xp + (size_t)(t + 4) * strideT;
#pragma unroll
                for (int q = 0; q < 4; q++) buf[k][q] = xn[q * HID];
            }
            const u64* h2 = reinterpret_cast<const u64*>(hbw[w]);
            u64 aA0 = pk(0.f,0.f), aA1 = aA0, aA2 = aA0, aA3 = aA0;
            u64 aB0 = aA0, aB1 = aA0, aB2 = aA0, aB3 = aA0;
#pragma unroll
            for (int j = 0; j < 8; j++) {
                u64 hv = h2[j];
                fma2(aA0, whh[0][j], hv); fma2(aA1, whh[1][j], hv);
                fma2(aA2, whh[2][j], hv); fma2(aA3, whh[3][j], hv);
            }
#pragma unroll
            for (int j = 8; j < 16; j++) {
                u64 hv = h2[j];
                fma2(aB0, whh[0][j], hv); fma2(aB1, whh[1][j], hv);
                fma2(aB2, whh[2][j], hv); fma2(aB3, whh[3][j], hv);
            }
            g0 += hsum(add2(aA0, aB0));
            g1 += hsum(add2(aA1, aB1));
            g2 += hsum(add2(aA2, aB2));
            g3 += hsum(add2(aA3, aB3));

            float iv = sigm(g0), fv = sigm(g1);
            float gv = tanh_hw(g2), ov = sigm(g3);
            c = fmaf(fv, c, iv * gv);
            float ot = ov * tanh_hw(c);

            ots[u] = ot;
            __syncwarp();
            const u64* o2 = reinterpret_cast<const u64*>(ots) + w * 16;
            u64 pA = pk(0.f,0.f), pB = pA;
#pragma unroll
            for (int j = 0; j < 8; j++)  fma2(pA, whr[j], o2[j]);
#pragma unroll
            for (int j = 8; j < 16; j++) fma2(pB, whr[j], o2[j]);
            hp[k & 1][w][l] = hsum(add2(pA, pB));
            __syncthreads();
            const float (*hpv)[32] = hp[k & 1];
            float hv = (hpv[0][l] + hpv[1][l]) + (hpv[2][l] + hpv[3][l]);
            hbw[w][l] = hv;
            if (EMIT_H0) {
                if (w == 0) h0out[((size_t)t * BATCH + b) * PROJ + l] = hv;
            }
            if (EMIT_OUT) {
                if (w == 0) {
                    float val = fmaxf(hv, 0.f) * w2v;
#pragma unroll
                    for (int off = 16; off; off >>= 1)
                        val += __shfl_down_sync(0xffffffffu, val, off);
                    if (l == 0) {
                        float z = fmaxf(val + b2v, 0.f);
                        out[(size_t)b * T_LEN + t] = sigm_acc(z);
                    }
                }
            }
            __syncwarp();
        }
        if (EMIT_H0) {
            if (w == 0) {
                __threadfence();
                __syncwarp();
                if (l == 0) wm_store(wm_out, t4 * 4 + 4);
            }
        }
    }
}

// ---------------- 4-stage pipelined scan over 256 blocks ----------------
// roles: 0-63 C0, 64-127 G(xi1), 128-191 C1, 192-255 X(xi0 producer)
__global__ void __launch_bounds__(128, 1) scan4(
    const float* __restrict__ x,
    const float* __restrict__ Wih0,
    const float* __restrict__ bih0, const float* __restrict__ bhh0,
    const float* __restrict__ Whh0, const float* __restrict__ Whr0,
    const float* __restrict__ Wih1,
    const float* __restrict__ bih1, const float* __restrict__ bhh1,
    const float* __restrict__ Whh1, const float* __restrict__ Whr1,
    const float* __restrict__ W2,   const float* __restrict__ b2,
    float* __restrict__ out)
{
    const int role = blockIdx.x >> 6;      // 0: C0, 1: G, 2: C1, 3: X
    const int b    = blockIdx.x & 63;
    const int u    = threadIdx.x;

    if (role == 0) {
        cell_phase<true, false>(b, g_xi, g_wmx + b, g_wm0 + b,
                                Whh0, Whr0, nullptr, nullptr, g_h0, nullptr);
    } else if (role == 1) {
        // ---- G: xi1 gemv, 8-step windows (R7-proven) ----
        __shared__ __align__(16) float h0win[8][32];

        u64 wih[4][16];
        float biasq[4];
#pragma unroll
        for (int q = 0; q < 4; q++) {
            const u64* p = reinterpret_cast<const u64*>(Wih1 + (q * HID + u) * PROJ);
#pragma unroll
            for (int j = 0; j < 16; j++) wih[q][j] = p[j];
            biasq[q] = bih1[q * HID + u] + bhh1[q * HID + u];
        }

        int wmv = 0;
        for (int w8 = 0; w8 < T_LEN / 8; w8++) {
            const int need = w8 * 8 + 8;
            while (wmv < need) { wmv = wm_load(&g_wm0[b]); if (wmv < need) __nanosleep(100); }
#pragma unroll
            for (int r = 0; r < 2; r++) {
                int idx = u + r * 128;
                int tt = idx >> 5, jj = idx & 31;
                h0win[tt][jj] =
                    g_h0[((size_t)(w8 * 8 + tt) * BATCH + b) * PROJ + jj];
            }
            __syncthreads();
#pragma unroll 2
            for (int k = 0; k < 8; k++) {
                const u64* h2 = reinterpret_cast<const u64*>(h0win[k]);
                u64 aA0 = pk(0.f,0.f), aA1 = aA0, aA2 = aA0, aA3 = aA0;
                u64 aB0 = aA0, aB1 = aA0, aB2 = aA0, aB3 = aA0;
#pragma unroll
                for (int j = 0; j < 8; j++) {
                    u64 hv = h2[j];
                    fma2(aA0, wih[0][j], hv); fma2(aA1, wih[1][j], hv);
                    fma2(aA2, wih[2][j], hv); fma2(aA3, wih[3][j], hv);
                }
#pragma unroll
                for (int j = 8; j < 16; j++) {
                    u64 hv = h2[j];
                    fma2(aB0, wih[0][j], hv); fma2(aB1, wih[1][j], hv);
                    fma2(aB2, wih[2][j], hv); fma2(aB3, wih[3][j], hv);
                }
                float* xo = g_xi1 + ((size_t)(w8 * 8 + k) * BATCH + b) * G4;
                xo[u]           = biasq[0] + hsum(add2(aA0, aB0));
                xo[HID + u]     = biasq[1] + hsum(add2(aA1, aB1));
                xo[2*HID + u]   = biasq[2] + hsum(add2(aA2, aB2));
                xo[3*HID + u]   = biasq[3] + hsum(add2(aA3, aB3));
            }
            __threadfence();
            __syncthreads();
            if (u == 0) wm_store(&g_wm1[b], w8 * 8 + 8);
        }
    } else if (role == 2) {
        cell_phase<false, true>(b, g_xi1, g_wm1 + b, nullptr,
                                Whh1, Whr1, W2, b2, nullptr, out);
    } else {
        // ---- X: register-lean xi0 producer ----
        // per tile (8 steps): stage x to smem, then 2 passes x 2 gate-rows/thread.
        __shared__ __align__(16) u64 xwin[2][80][4];   // [buf][feature][t-pair]

        const size_t st = (size_t)BATCH * G4;

        // stage tile 0
        {
            for (int idx = u; idx < 160; idx += 128) {
                int f = idx >> 1, half = idx & 1;
                float4 v = *reinterpret_cast<const float4*>(
                    x + (size_t)(b * 80 + f) * T_LEN + half * 4);
                xwin[0][f][half * 2]     = pk(v.x, v.y);
                xwin[0][f][half * 2 + 1] = pk(v.z, v.w);
            }
        }
        __syncthreads();

        for (int tile = 0; tile < T_LEN / 8; tile++) {
            const int par = tile & 1;
            // prefetch + stage next tile into other buffer
            if (tile + 1 < T_LEN / 8) {
                for (int idx = u; idx < 160; idx += 128) {
                    int f = idx >> 1, half = idx & 1;
                    float4 v = *reinterpret_cast<const float4*>(
                        x + (size_t)(b * 80 + f) * T_LEN + (tile + 1) * 8 + half * 4);
                    xwin[par ^ 1][f][half * 2]     = pk(v.x, v.y);
                    xwin[par ^ 1][f][half * 2 + 1] = pk(v.z, v.w);
                }
            }
            // 2 passes, 2 gate rows per thread per pass
#pragma unroll
            for (int pass = 0; pass < 2; pass++) {
                const int r0i = pass * 2 * HID + u;        // gate rows r0i, r0i+HID
                u64 acc[2][4];
                {
                    float bA = bih0[r0i] + bhh0[r0i];
                    float bB = bih0[r0i + HID] + bhh0[r0i + HID];
#pragma unroll
                    for (int p = 0; p < 4; p++) {
                        acc[0][p] = pk(bA, bA);
                        acc[1][p] = pk(bB, bB);
                    }
                }
                const float* wrA = Wih0 + (size_t)r0i * 80;
                const float* wrB = Wih0 + (size_t)(r0i + HID) * 80;
#pragma unroll 2
                for (int f4 = 0; f4 < 20; f4++) {
                    u64 xv[4][4];
#pragma unroll
                    for (int ff = 0; ff < 4; ff++) {
                        uint32_t sa = (uint32_t)__cvta_generic_to_shared(&xwin[par][f4 * 4 + ff][0]);
                        asm("ld.shared.v2.u64 {%0, %1}, [%2];"    : "=l"(xv[ff][0]), "=l"(xv[ff][1]) : "r"(sa));
                        asm("ld.shared.v2.u64 {%0, %1}, [%2+16];" : "=l"(xv[ff][2]), "=l"(xv[ff][3]) : "r"(sa));
                    }
                    float4 wa = *reinterpret_cast<const float4*>(wrA + f4 * 4);
                    float4 wb = *reinterpret_cast<const float4*>(wrB + f4 * 4);
#pragma unroll
                    for (int p = 0; p < 4; p++) {
                        fma2(acc[0][p], pk(wa.x, wa.x), xv[0][p]);
                        fma2(acc[0][p], pk(wa.y, wa.y), xv[1][p]);
                        fma2(acc[0][p], pk(wa.z, wa.z), xv[2][p]);
                        fma2(acc[0][p], pk(wa.w, wa.w), xv[3][p]);
                        fma2(acc[1][p], pk(wb.x, wb.x), xv[0][p]);
                        fma2(acc[1][p], pk(wb.y, wb.y), xv[1][p]);
                        fma2(acc[1][p], pk(wb.z, wb.z), xv[2][p]);
                        fma2(acc[1][p], pk(wb.w, wb.w), xv[3][p]);
                    }
                }
                float* xo = g_xi + ((size_t)tile * 8 * BATCH + b) * G4;
#pragma unroll
                for (int rr = 0; rr < 2; rr++) {
                    int r = r0i + rr * HID;
#pragma unroll
                    for (int p = 0; p < 4; p++) {
                        float lo, hi; upk(acc[rr][p], lo, hi);
                        xo[(size_t)(2 * p)     * st + r] = lo;
                        xo[(size_t)(2 * p + 1) * st + r] = hi;
                    }
                }
            }
            __threadfence();
            __syncthreads();
            if (u == 0) wm_store(&g_wmx[b], tile * 8 + 8);
        }
    }
}

// ---------------- launch ----------------
extern "C" void kernel_launch(void* const* d_in, const int* in_sizes, int n_in,
                              void* d_out, int out_size)
{
    const float* x    = (const float*)d_in[0];
    const float* Wih0 = (const float*)d_in[1];
    const float* Whh0 = (const float*)d_in[2];
    const float* bih0 = (const float*)d_in[3];
    const float* bhh0 = (const float*)d_in[4];
    const float* Whr0 = (const float*)d_in[5];
    const float* Wih1 = (const float*)d_in[6];
    const float* Whh1 = (const float*)d_in[7];
    const float* bih1 = (const float*)d_in[8];
    const float* bhh1 = (const float*)d_in[9];
    const float* Whr1 = (const float*)d_in[10];
    const float* W2   = (const float*)d_in[11];
    const float* b2   = (const float*)d_in[12];
    float* out = (float*)d_out;

    init_wm<<<1, 64>>>();
    scan4<<<256, 128>>>(x, Wih0, bih0, bhh0, Whh0, Whr0,
                        Wih1, bih1, bhh1, Whh1, Whr1,
                        W2, b2, out);
}

// round 14
// speedup vs baseline: 1.5634x; 1.5634x over previous
#include <cuda_runtime.h>
#include <cstdint>

#define T_LEN 6000
#define BATCH 64
#define HID   128
#define PROJ  32
#define G4    512

typedef unsigned long long u64;

// ---------------- scratch ----------------
__device__ float g_xi [(size_t)T_LEN * BATCH * G4];    // xi0 (gemm -> C0)
__device__ float g_xi1[(size_t)T_LEN * BATCH * G4];    // xi1 (G -> C1)
__device__ float g_h0 [(size_t)T_LEN * BATCH * PROJ];  // h0  (C0 -> G)
__device__ int   g_wm0[BATCH];                         // h0 watermark
__device__ int   g_wm1[BATCH];                         // xi1 watermark

// ---------------- f32x2 helpers ----------------
__device__ __forceinline__ u64 pk(float lo, float hi) {
    u64 r;
    asm("mov.b64 %0, {%1, %2};" : "=l"(r) : "f"(lo), "f"(hi));
    return r;
}
__device__ __forceinline__ void upk(u64 a, float& lo, float& hi) {
    asm("mov.b64 {%0, %1}, %2;" : "=f"(lo), "=f"(hi) : "l"(a));
}
__device__ __forceinline__ void fma2(u64& d, u64 a, u64 b) {
    asm("fma.rn.f32x2 %0, %1, %2, %3;" : "=l"(d) : "l"(a), "l"(b), "l"(d));
}
__device__ __forceinline__ u64 add2(u64 a, u64 b) {
    u64 r;
    asm("add.rn.f32x2 %0, %1, %2;" : "=l"(r) : "l"(a), "l"(b));
    return r;
}
__device__ __forceinline__ float hsum(u64 a) {
    float lo, hi; upk(a, lo, hi); return lo + hi;
}

// ---------------- activations ----------------
__device__ __forceinline__ float tanh_hw(float x) {
    float r; asm("tanh.approx.f32 %0, %1;" : "=f"(r) : "f"(x)); return r;
}
__device__ __forceinline__ float sigm(float x) {
    return fmaf(tanh_hw(x * 0.5f), 0.5f, 0.5f);
}
__device__ __forceinline__ float ex2_(float x) {
    float r; asm("ex2.approx.f32 %0, %1;" : "=f"(r) : "f"(x)); return r;
}
__device__ __forceinline__ float rcp_(float x) {
    float r; asm("rcp.approx.f32 %0, %1;" : "=f"(r) : "f"(x)); return r;
}
__device__ __forceinline__ float sigm_acc(float x) {
    return rcp_(1.f + ex2_(-x * 1.4426950408889634f));
}

// ---------------- flag ops ----------------
__device__ __forceinline__ void wm_store(int* p, int v) {
    asm volatile("st.release.gpu.global.s32 [%0], %1;" :: "l"(p), "r"(v) : "memory");
}
__device__ __forceinline__ int wm_load(const int* p) {
    int v;
    asm volatile("ld.acquire.gpu.global.s32 %0, [%1];" : "=r"(v) : "l"(p) : "memory");
    return v;
}
__device__ __forceinline__ void barh(int half) {
    asm volatile("bar.sync %0, 128;" :: "r"(1 + half) : "memory");
}

__global__ void init_wm() {
    if (threadIdx.x < BATCH) { g_wm0[threadIdx.x] = 0; g_wm1[threadIdx.x] = 0; }
}

// ---------------- GEMM0 (proven) ----------------
__global__ void __launch_bounds__(512, 1) gemm_xi0(
    const float* __restrict__ x, const float* __restrict__ Wih,
    const float* __restrict__ bih, const float* __restrict__ bhh,
    float* __restrict__ xi)
{
    int b  = blockIdx.y;
    int t0 = blockIdx.x * 128;
    int g  = threadIdx.x;

    __shared__ u64 xs2[80][64];

    for (int idx = g; idx < 80 * 32; idx += 512) {
        int f = idx >> 5, i4 = idx & 31;
        int t = t0 + i4 * 4;
        const float* src = x + ((size_t)b * 80 + f) * T_LEN + t;
        float4 v;
        if (t + 3 < T_LEN) {
            v = *reinterpret_cast<const float4*>(src);
        } else {
            v.x = (t     < T_LEN) ? src[0] : 0.f;
            v.y = (t + 1 < T_LEN) ? src[1] : 0.f;
            v.z = (t + 2 < T_LEN) ? src[2] : 0.f;
            v.w = (t + 3 < T_LEN) ? src[3] : 0.f;
        }
        xs2[f][i4 * 2]     = pk(v.x, v.y);
        xs2[f][i4 * 2 + 1] = pk(v.z, v.w);
    }

    float w[80];
#pragma unroll
    for (int f = 0; f < 80; f++) w[f] = Wih[g * 80 + f];
    float bias = bih[g] + bhh[g];
    __syncthreads();

    int tmax = min(128, T_LEN - t0);
    const size_t st = (size_t)BATCH * G4;

    for (int i8 = 0; i8 < tmax / 8; i8++) {
        u64 a0 = pk(bias, bias), a1 = a0, a2 = a0, a3 = a0;
#pragma unroll
        for (int f = 0; f < 80; f++) {
            u64 pA, pB, pC, pD;
            uint32_t sa = (uint32_t)__cvta_generic_to_shared(&xs2[f][i8 * 4]);
            asm("ld.shared.v2.u64 {%0, %1}, [%2];"    : "=l"(pA), "=l"(pB) : "r"(sa));
            asm("ld.shared.v2.u64 {%0, %1}, [%2+16];" : "=l"(pC), "=l"(pD) : "r"(sa));
            u64 w2 = pk(w[f], w[f]);
            fma2(a0, w2, pA); fma2(a1, w2, pB);
            fma2(a2, w2, pC); fma2(a3, w2, pD);
        }
        size_t o = ((size_t)(t0 + i8 * 8) * BATCH + b) * G4 + g;
        float lo, hi;
        upk(a0, lo, hi); xi[o]          = lo; xi[o + st]     = hi;
        upk(a1, lo, hi); xi[o + 2 * st] = lo; xi[o + 3 * st] = hi;
        upk(a2, lo, hi); xi[o + 4 * st] = lo; xi[o + 5 * st] = hi;
        upk(a3, lo, hi); xi[o + 6 * st] = lo; xi[o + 7 * st] = hi;
    }
}

// ---------------- LSTM cell body: one HALF (128 threads) of a 256-thread block ----
// Two independent batches per block; half h uses named barrier 1+h and its own
// slice of shared state. No block-wide sync anywhere.
struct CellSmem {
    float ots[2][128];
    float hp [2][2][4][32];
    float hbw[2][4][32];
};

template<bool EMIT_H0, bool EMIT_OUT>
__device__ __forceinline__ void cell_phase(
    CellSmem& S, int half, int b,
    const float* __restrict__ xsrc, const int* __restrict__ wm_in,
    int* __restrict__ wm_out, const float* __restrict__ Whh,
    const float* __restrict__ Whr, const float* __restrict__ W2,
    const float* __restrict__ b2, float* __restrict__ h0out,
    float* __restrict__ out)
{
    const int u = threadIdx.x & 127;
    const int w = u >> 5, l = u & 31;

    u64 whh[4][16];
#pragma unroll
    for (int q = 0; q < 4; q++) {
        const u64* p = reinterpret_cast<const u64*>(Whh + (q * HID + u) * PROJ);
#pragma unroll
        for (int j = 0; j < 16; j++) whh[q][j] = p[j];
    }
    u64 whr[16];
    {
        const u64* wr = reinterpret_cast<const u64*>(Whr + l * HID + w * 32);
#pragma unroll
        for (int j = 0; j < 16; j++) whr[j] = wr[j];
    }
    float w2v = 0.f, b2v = 0.f;
    if (EMIT_OUT) { w2v = W2[l]; b2v = b2[0]; }

    S.hbw[half][w][l] = 0.f;
    float c = 0.f;
    barh(half);

    const size_t strideT = (size_t)BATCH * G4;
    const float* xp = xsrc + (size_t)b * G4 + u;

    int wmv = 0;
    if (wm_in) { while ((wmv = wm_load(wm_in)) < 8) __nanosleep(200); }

    float buf[4][4];
#pragma unroll
    for (int k = 0; k < 4; k++) {
        const float* xn = xp + (size_t)k * strideT;
#pragma unroll
        for (int q = 0; q < 4; q++) buf[k][q] = xn[q * HID];
    }

    for (int t4 = 0; t4 < T_LEN / 4; t4++) {
        if (wm_in && t4) {
            int need = t4 * 4 + 8; if (need > T_LEN) need = T_LEN;
            while (wmv < need) { wmv = wm_load(wm_in); if (wmv < need) __nanosleep(100); }
        }
#pragma unroll
        for (int k = 0; k < 4; k++) {
            const int t = t4 * 4 + k;
            float g0 = buf[k][0], g1 = buf[k][1], g2 = buf[k][2], g3 = buf[k][3];
            if (t + 4 < T_LEN) {
                const float* xn = xp + (size_t)(t + 4) * strideT;
#pragma unroll
                for (int q = 0; q < 4; q++) buf[k][q] = xn[q * HID];
            }
            const u64* h2 = reinterpret_cast<const u64*>(S.hbw[half][w]);
            u64 aA0 = pk(0.f,0.f), aA1 = aA0, aA2 = aA0, aA3 = aA0;
            u64 aB0 = aA0, aB1 = aA0, aB2 = aA0, aB3 = aA0;
#pragma unroll
            for (int j = 0; j < 8; j++) {
                u64 hv = h2[j];
                fma2(aA0, whh[0][j], hv); fma2(aA1, whh[1][j], hv);
                fma2(aA2, whh[2][j], hv); fma2(aA3, whh[3][j], hv);
            }
#pragma unroll
            for (int j = 8; j < 16; j++) {
                u64 hv = h2[j];
                fma2(aB0, whh[0][j], hv); fma2(aB1, whh[1][j], hv);
                fma2(aB2, whh[2][j], hv); fma2(aB3, whh[3][j], hv);
            }
            g0 += hsum(add2(aA0, aB0));
            g1 += hsum(add2(aA1, aB1));
            g2 += hsum(add2(aA2, aB2));
            g3 += hsum(add2(aA3, aB3));

            float iv = sigm(g0), fv = sigm(g1);
            float gv = tanh_hw(g2), ov = sigm(g3);
            c = fmaf(fv, c, iv * gv);
            float ot = ov * tanh_hw(c);

            S.ots[half][u] = ot;
            __syncwarp();
            const u64* o2 = reinterpret_cast<const u64*>(S.ots[half]) + w * 16;
            u64 pA = pk(0.f,0.f), pB = pA;
#pragma unroll
            for (int j = 0; j < 8; j++)  fma2(pA, whr[j], o2[j]);
#pragma unroll
            for (int j = 8; j < 16; j++) fma2(pB, whr[j], o2[j]);
            S.hp[half][k & 1][w][l] = hsum(add2(pA, pB));
            barh(half);
            const float (*hpv)[32] = S.hp[half][k & 1];
            float hv = (hpv[0][l] + hpv[1][l]) + (hpv[2][l] + hpv[3][l]);
            S.hbw[half][w][l] = hv;
            if (EMIT_H0) {
                if (w == 0) h0out[((size_t)t * BATCH + b) * PROJ + l] = hv;
            }
            if (EMIT_OUT) {
                if (w == 0) {
                    float val = fmaxf(hv, 0.f) * w2v;
#pragma unroll
                    for (int off = 16; off; off >>= 1)
                        val += __shfl_down_sync(0xffffffffu, val, off);
                    if (l == 0) {
                        float z = fmaxf(val + b2v, 0.f);
                        out[(size_t)b * T_LEN + t] = sigm_acc(z);
                    }
                }
            }
            __syncwarp();
        }
        if (EMIT_H0) {
            if (w == 0) {
                __threadfence();
                __syncwarp();
                if (l == 0) wm_store(wm_out, t4 * 4 + 4);
            }
        }
    }
}

// ---------------- scan over 128 blocks x 256 threads ----------------
// bids 0-31: C0 (batches 2b, 2b+1), 32-63: C1 (batches 2(b-32), +1), 64-127: G (batch b-64)
__global__ void __launch_bounds__(256, 1) scan3(
    const float* __restrict__ Whh0, const float* __restrict__ Whr0,
    const float* __restrict__ Wih1,
    const float* __restrict__ bih1, const float* __restrict__ bhh1,
    const float* __restrict__ Whh1, const float* __restrict__ Whr1,
    const float* __restrict__ W2,   const float* __restrict__ b2,
    float* __restrict__ out)
{
    const int bid = blockIdx.x;

    if (bid < 64) {
        __shared__ CellSmem S;
        const int half = threadIdx.x >> 7;
        if (bid < 32) {
            const int b = bid * 2 + half;
            cell_phase<true, false>(S, half, b, g_xi, nullptr, g_wm0 + b,
                                    Whh0, Whr0, nullptr, nullptr, g_h0, nullptr);
        } else {
            const int b = (bid - 32) * 2 + half;
            cell_phase<false, true>(S, half, b, g_xi1, g_wm1 + b, nullptr,
                                    Whh1, Whr1, W2, b2, nullptr, out);
        }
    } else {
        // ---- G: xi1 gemv, 256 threads, 2 gate-rows per thread ----
        const int b = bid - 64;
        const int v = threadIdx.x;
        const int rA = v, rB = v + 256;

        __shared__ __align__(16) float h0win[8][32];

        u64 wgtA[16], wgtB[16];
        {
            const u64* pA = reinterpret_cast<const u64*>(Wih1 + (size_t)rA * PROJ);
            const u64* pB = reinterpret_cast<const u64*>(Wih1 + (size_t)rB * PROJ);
#pragma unroll
            for (int j = 0; j < 16; j++) { wgtA[j] = pA[j]; wgtB[j] = pB[j]; }
        }
        float biasA = bih1[rA] + bhh1[rA];
        float biasB = bih1[rB] + bhh1[rB];

        int wmv = 0;
        for (int w8 = 0; w8 < T_LEN / 8; w8++) {
            const int need = w8 * 8 + 8;
            while (wmv < need) { wmv = wm_load(&g_wm0[b]); if (wmv < need) __nanosleep(100); }
            // load h0 window: 256 entries, exactly 1 per thread
            {
                int tt = v >> 5, jj = v & 31;
                h0win[tt][jj] =
                    g_h0[((size_t)(w8 * 8 + tt) * BATCH + b) * PROJ + jj];
            }
            __syncthreads();
#pragma unroll 2
            for (int k = 0; k < 8; k++) {
                const u64* h2 = reinterpret_cast<const u64*>(h0win[k]);
                u64 aA0 = pk(0.f,0.f), aA1 = aA0;
                u64 aB0 = aA0, aB1 = aA0;
#pragma unroll
                for (int j = 0; j < 8; j++) {
                    u64 hv = h2[j];
                    fma2(aA0, wgtA[j], hv); fma2(aB0, wgtB[j], hv);
                }
#pragma unroll
                for (int j = 8; j < 16; j++) {
                    u64 hv = h2[j];
                    fma2(aA1, wgtA[j], hv); fma2(aB1, wgtB[j], hv);
                }
                float* xo = g_xi1 + ((size_t)(w8 * 8 + k) * BATCH + b) * G4;
                xo[rA] = biasA + hsum(add2(aA0, aA1));
                xo[rB] = biasB + hsum(add2(aB0, aB1));
            }
            __threadfence();
            __syncthreads();
            if (v == 0) wm_store(&g_wm1[b], w8 * 8 + 8);
        }
    }
}

// ---------------- launch ----------------
extern "C" void kernel_launch(void* const* d_in, const int* in_sizes, int n_in,
                              void* d_out, int out_size)
{
    const float* x    = (const float*)d_in[0];
    const float* Wih0 = (const float*)d_in[1];
    const float* Whh0 = (const float*)d_in[2];
    const float* bih0 = (const float*)d_in[3];
    const float* bhh0 = (const float*)d_in[4];
    const float* Whr0 = (const float*)d_in[5];
    const float* Wih1 = (const float*)d_in[6];
    const float* Whh1 = (const float*)d_in[7];
    const float* bih1 = (const float*)d_in[8];
    const float* bhh1 = (const float*)d_in[9];
    const float* Whr1 = (const float*)d_in[10];
    const float* W2   = (const float*)d_in[11];
    const float* b2   = (const float*)d_in[12];
    float* out = (float*)d_out;

    float* xi;
    cudaGetSymbolAddress((void**)&xi, g_xi);

    dim3 gridG((T_LEN + 127) / 128, BATCH);

    init_wm<<<1, 64>>>();
    gemm_xi0<<<gridG, 512>>>(x, Wih0, bih0, bhh0, xi);
    scan3<<<128, 256>>>(Whh0, Whr0,
                        Wih1, bih1, bhh1, Whh1, Whr1,
                        W2, b2, out);
}